// round 12
// baseline (speedup 1.0000x reference)
#include <cuda_runtime.h>
#include <cuda_fp16.h>

// Correlation as banded fp16 GEMM (HMMA, fp32 accum), FUSED conversion:
// out[b, di*9+dj, y, x] = (1/64) * sum_c f1[b,c,y,x] * f2pad[b,c,y+di,x+dj]
// Per (b,y,di): C[x,x'] = sum_c f1[c,x]*f2[c,x']; dj = x'-x+4.
// CTA = (b, 4 y-rows, 32 x): m16n8k16 tiles on the 9-wide diagonal band.
// f2 converted fp32->fp16 inside the CTA prologue (no pre-pass, no scratch).

#define BB 4
#define CC 64
#define HH 192
#define WW 448
#define DD 4

#define YTI 4
#define XTI 32
#define NTHR 256

// smem layout (bytes)
#define F1S_KSTRIDE 272                   // 4y*32x*2B + 16 (16 mod 128 -> LDSM conflict-free)
#define F1S_BYTES   (CC * F1S_KSTRIDE)    // 17408
#define F2S_ROWB    96                    // 48 halves/row (40 real)
#define F2S_KSTRIDE (12*F2S_ROWB + 16)    // 1168 (16 mod 128)
#define F2S_OFF     F1S_BYTES
#define F2S_BYTES   (CC * F2S_KSTRIDE)    // 74752
#define EPI_OFF     (F2S_OFF + F2S_BYTES) // 92160
#define EPI_SZ      (9*YTI*XTI*4)         // 4608
#define SMEM_TOTAL  (EPI_OFF + 2*EPI_SZ)  // 101376

__global__ __launch_bounds__(NTHR, 2)
void corr_mma(const float* __restrict__ f1,
              const float* __restrict__ f2,
              float* __restrict__ out)
{
    extern __shared__ char smem[];
    const unsigned sb = (unsigned)__cvta_generic_to_shared(smem);
    const int tid  = threadIdx.x;
    const int lane = tid & 31;
    const int w    = tid >> 5;        // 8 warps
    const int yy   = w >> 1;          // warp's y row (0..3)
    const int mb   = (w & 1) * 16;    // warp's m-tile base pixel (0 or 16)
    const int b  = blockIdx.z;
    const int y0 = blockIdx.y * YTI;
    const int x0 = blockIdx.x * XTI;

    // ---- f2 tile: fp32 LDG -> half -> STS. 64k x 12 rows x 40 halves ----
    // 7680 float4 chunks -> 30 per thread. Per-chunk full-in/out predicate.
    {
        const float* f2b = f2 + (size_t)b * CC * HH * WW;
#pragma unroll
        for (int i = 0; i < 30; i++) {
            const int c  = tid + i * 256;
            const int k  = c / 120;
            const int rm = c - k * 120;
            const int r  = rm / 10;
            const int h  = rm - r * 10;
            const int gy = y0 - DD + r;
            const int gx = x0 - DD + 4 * h;
            float4 v = make_float4(0.f, 0.f, 0.f, 0.f);
            if ((unsigned)gy < HH && (unsigned)gx < WW)
                v = *(const float4*)(f2b + ((size_t)k * HH + gy) * WW + gx);
            __half2 h0 = __floats2half2_rn(v.x, v.y);
            __half2 h1 = __floats2half2_rn(v.z, v.w);
            unsigned s = sb + F2S_OFF + k * F2S_KSTRIDE + r * F2S_ROWB + h * 8;
            asm volatile("st.shared.v2.b32 [%0], {%1,%2};"
                         :: "r"(s), "r"(*(unsigned*)&h0), "r"(*(unsigned*)&h1));
        }
    }

    // ---- f1 tile: fp32 LDG -> half -> STS. 2048 float4 chunks -> 8/thread ----
    {
        const float* f1b = f1 + (size_t)b * CC * HH * WW;
#pragma unroll
        for (int i = 0; i < 8; i++) {
            const int id = tid + i * 256;
            const int k  = id >> 5;
            const int rm = id & 31;
            const int ry = rm >> 3;
            const int h  = rm & 7;
            float4 v = *(const float4*)(f1b + ((size_t)k * HH + y0 + ry) * WW + x0 + h * 4);
            __half2 h0 = __floats2half2_rn(v.x, v.y);
            __half2 h1 = __floats2half2_rn(v.z, v.w);
            unsigned s = sb + k * F1S_KSTRIDE + (ry * 32 + h * 4) * 2;
            asm volatile("st.shared.v2.b32 [%0], {%1,%2};"
                         :: "r"(s), "r"(*(unsigned*)&h0), "r"(*(unsigned*)&h1));
        }
    }

    __syncthreads();

    // ---- ldmatrix lane addresses (trans: smem is [k][m] / [k][n]) ----
    const int gq = lane >> 3, lr = lane & 7;
    const unsigned aAddr = sb + (((gq & 2) << 2) + lr) * F1S_KSTRIDE
                         + (yy * 32 + mb + ((gq & 1) << 3)) * 2;
    const unsigned bAddr = sb + F2S_OFF + (((gq & 1) << 3) + lr) * F2S_KSTRIDE
                         + yy * F2S_ROWB + mb * 2;

    // A fragments: loaded once, reused for all 9 di
    unsigned a[4][4];
#pragma unroll
    for (int ks = 0; ks < 4; ks++)
        asm volatile("ldmatrix.sync.aligned.m8n8.x4.trans.shared.b16 {%0,%1,%2,%3}, [%4];"
            : "=r"(a[ks][0]), "=r"(a[ks][1]), "=r"(a[ks][2]), "=r"(a[ks][3])
            : "r"(aAddr + ks * 16 * F1S_KSTRIDE));

    const int g = lane >> 2, tg = lane & 3;
    const float scale = 1.f / 64.f;

    for (int di = 0; di < 9; di++) {
        float* epi = (float*)(smem + EPI_OFF + (di & 1) * EPI_SZ);

        float acc[3][4];
#pragma unroll
        for (int q = 0; q < 3; q++)
#pragma unroll
            for (int p = 0; p < 4; p++) acc[q][p] = 0.f;

#pragma unroll
        for (int q = 0; q < 3; q++) {
#pragma unroll
            for (int ks = 0; ks < 4; ks++) {
                unsigned b0, b1;
                asm volatile("ldmatrix.sync.aligned.m8n8.x2.trans.shared.b16 {%0,%1}, [%2];"
                    : "=r"(b0), "=r"(b1)
                    : "r"(bAddr + di * F2S_ROWB + q * 16 + ks * 16 * F2S_KSTRIDE));
                asm volatile(
                    "mma.sync.aligned.m16n8k16.row.col.f32.f16.f16.f32 "
                    "{%0,%1,%2,%3}, {%4,%5,%6,%7}, {%8,%9}, {%0,%1,%2,%3};"
                    : "+f"(acc[q][0]), "+f"(acc[q][1]), "+f"(acc[q][2]), "+f"(acc[q][3])
                    : "r"(a[ks][0]), "r"(a[ks][1]), "r"(a[ks][2]), "r"(a[ks][3]),
                      "r"(b0), "r"(b1));
            }
        }

        // band extraction: dj = n_local - m_local, keep 0..8
#pragma unroll
        for (int q = 0; q < 3; q++) {
#pragma unroll
            for (int p = 0; p < 4; p++) {
                int m  = g + ((p >> 1) << 3);
                int dj = 8 * q + 2 * tg + (p & 1) - m;
                if ((unsigned)dj <= 8u)
                    epi[(dj * YTI + yy) * XTI + mb + m] = acc[q][p];
            }
        }
        __syncthreads();   // epi[di&1] complete; also protects epi[di&1] from
                           // being overwritten at di+2 (writers pass barrier di+1
                           // only after this di's readers finished their STGs).

        // coalesced store of 9 x 4 x 32 floats
#pragma unroll
        for (int i = 0; i < 5; i++) {
            int idx = tid + i * 256;
            if (idx < 9 * YTI * XTI) {
                int dj  = idx / (YTI * XTI);
                int rem = idx - dj * (YTI * XTI);
                int ry = rem >> 5, xx = rem & 31;
                out[((size_t)(b * 81 + di * 9 + dj) * HH + y0 + ry) * WW + x0 + xx]
                    = epi[idx] * scale;
            }
        }
        // no second barrier: next di writes the other epi buffer
    }
}

extern "C" void kernel_launch(void* const* d_in, const int* in_sizes, int n_in,
                              void* d_out, int out_size)
{
    const float* f1 = (const float*)d_in[0];
    const float* f2 = (const float*)d_in[1];
    float* out = (float*)d_out;

    cudaFuncSetAttribute(corr_mma,
                         cudaFuncAttributeMaxDynamicSharedMemorySize, SMEM_TOTAL);
    dim3 grid(WW / XTI, HH / YTI, BB);   // 14 x 48 x 4 = 2688
    corr_mma<<<grid, NTHR, SMEM_TOTAL>>>(f1, f2, out);
}

// round 13
// speedup vs baseline: 1.3071x; 1.3071x over previous
#include <cuda_runtime.h>
#include <cuda_fp16.h>

// Correlation as banded fp16 GEMM (HMMA, fp32 accum), fully fused:
// out[b, di*9+dj, y, x] = (1/64) * sum_c f1[b,c,y,x] * f2pad[b,c,y+di,x+dj]
// Per (b,y,di): C[x,x'] = sum_c f1[c,x]*f2[c,x']; dj = x'-x+4.
// CTA = (b, 4 y-rows, 32 x): m16n8k16 tiles on the 9-wide diagonal band.
// f2 fp32 staged via cp.async ring (no regs), converted fp16 in-CTA (reader==writer,
// no extra barriers). Mainloop double-buffers B fragments across di.

#define BB 4
#define CC 64
#define HH 192
#define WW 448
#define DD 4

#define YTI 4
#define XTI 32
#define NTHR 256

// smem layout (bytes)
#define F1S_KSTRIDE 272                   // 256 + 16  (16 mod 128 -> LDSM conflict-free)
#define F1S_BYTES   (CC * F1S_KSTRIDE)    // 17408
#define F2S_ROWB    80                    // 40 halves/row, tight
#define F2S_KSTRIDE (12*F2S_ROWB + 16)    // 976 (80 mod 128 = odd*16 -> conflict-free)
#define F2S_OFF     F1S_BYTES
#define F2S_BYTES   (CC * F2S_KSTRIDE)    // 62464
#define STG_OFF     (F2S_OFF + F2S_BYTES) // 79872
#define KG          8                     // channels per staging group
#define NG          (CC / KG)             // 8
#define STG_CH_B    (12 * 160)            // 12 rows x 40 floats
#define STG_BYTES   (KG * STG_CH_B)       // 15360
#define NCHUNK      (KG * 12 * 10)        // 960 16B chunks per group
#define EPI_OFF     STG_OFF               // epi overlays staging after prologue
#define EPI_SZ      (9*YTI*XTI*4)         // 4608
#define SMEM_TOTAL  (STG_OFF + 2*STG_BYTES)  // 110592 -> 2 CTAs/SM

#define GSTRIDE_B   ((size_t)KG * HH * WW * 4)   // gmem bytes per channel-group

__device__ __forceinline__ void cp_async16z(unsigned saddr, const void* gaddr, int sz) {
    asm volatile("cp.async.cg.shared.global [%0], [%1], 16, %2;"
                 :: "r"(saddr), "l"(gaddr), "r"(sz));
}

__global__ __launch_bounds__(NTHR, 2)
void corr_mma(const float* __restrict__ f1,
              const float* __restrict__ f2,
              float* __restrict__ out)
{
    extern __shared__ char smem[];
    const unsigned sb = (unsigned)__cvta_generic_to_shared(smem);
    const int tid  = threadIdx.x;
    const int lane = tid & 31;
    const int w    = tid >> 5;        // 8 warps
    const int yy   = w >> 1;          // warp's y row (0..3)
    const int mb   = (w & 1) * 16;    // warp's m-tile base pixel (0 or 16)
    const int b  = blockIdx.z;
    const int y0 = blockIdx.y * YTI;
    const int x0 = blockIdx.x * XTI;

    const float* f2b = f2 + (size_t)b * CC * HH * WW;

    // ---- per-thread staging chunk descriptors (4 chunks; 4th only for tid<192) ----
    const char* gptr[4];
    int         zsz[4];
    unsigned    stgoff[4];
    unsigned    tileoff[4];
    const int nck = (tid < NCHUNK - 3 * NTHR) ? 4 : 3;
#pragma unroll
    for (int j = 0; j < 4; j++) {
        const int c = (j < nck) ? (tid + j * NTHR) : 0;
        const int ch = c / 120;
        const int rm = c - ch * 120;
        const int r  = rm / 10;
        const int h  = rm - r * 10;
        const int gy = y0 - DD + r;
        const int gx = x0 - DD + 4 * h;    // (x0-4) mult of 4 -> 16B aligned in gmem
        const bool ok = ((unsigned)gy < HH) && (gx >= 0) && (gx + 4 <= WW);
        gptr[j]    = (const char*)(f2b + (size_t)ch * HH * WW
                                   + (ok ? ((size_t)gy * WW + gx) : 0));
        zsz[j]     = ok ? 16 : 0;
        stgoff[j]  = ch * STG_CH_B + r * 160 + h * 16;
        tileoff[j] = ch * F2S_KSTRIDE + r * F2S_ROWB + h * 8;
    }

    auto prefetch = [&](int g, int buf) {
        if (g < NG) {
            const size_t gadd = (size_t)g * GSTRIDE_B;
            const unsigned sbb = sb + STG_OFF + buf * STG_BYTES;
#pragma unroll
            for (int j = 0; j < 4; j++)
                if (j < nck)
                    cp_async16z(sbb + stgoff[j], gptr[j] + gadd, zsz[j]);
        }
        asm volatile("cp.async.commit_group;" ::: "memory");
    };

    prefetch(0, 0);
    prefetch(1, 1);

    // ---- f1 tile: fp32 LDG -> half -> STS (overlaps staging cp.async) ----
    {
        const float* f1b = f1 + (size_t)b * CC * HH * WW;
#pragma unroll
        for (int i = 0; i < 8; i++) {
            const int id = tid + i * NTHR;    // 2048 float4 chunks: 64k x 4y x 8
            const int k  = id >> 5;
            const int rm = id & 31;
            const int ry = rm >> 3;
            const int h  = rm & 7;
            float4 v = *(const float4*)(f1b + ((size_t)k * HH + y0 + ry) * WW + x0 + h * 4);
            __half2 h0 = __floats2half2_rn(v.x, v.y);
            __half2 h1 = __floats2half2_rn(v.z, v.w);
            unsigned s = sb + k * F1S_KSTRIDE + (ry * 32 + h * 4) * 2;
            asm volatile("st.shared.v2.b32 [%0], {%1,%2};"
                         :: "r"(s), "r"(*(unsigned*)&h0), "r"(*(unsigned*)&h1));
        }
    }

    // ---- staged conversion: wait g, convert own chunks, prefetch g+2 ----
#pragma unroll
    for (int g = 0; g < NG; g++) {
        asm volatile("cp.async.wait_group 1;" ::: "memory");
        const int buf = g & 1;
        const char* stg = smem + STG_OFF + buf * STG_BYTES;
        char* tile = smem + F2S_OFF + g * (KG * F2S_KSTRIDE);
#pragma unroll
        for (int j = 0; j < 4; j++) {
            if (j < nck) {
                float4 v = *(const float4*)(stg + stgoff[j]);
                __half2 h0 = __floats2half2_rn(v.x, v.y);
                __half2 h1 = __floats2half2_rn(v.z, v.w);
                uint2 o = make_uint2(*(unsigned*)&h0, *(unsigned*)&h1);
                *(uint2*)(tile + tileoff[j]) = o;
            }
        }
        prefetch(g + 2, buf);
    }

    __syncthreads();   // f1 + f2 fp16 tiles visible to all; staging dead (epi overlay ok)

    // ---- ldmatrix lane addresses (trans: smem is [k][m] / [k][n]) ----
    const int gq = lane >> 3, lr = lane & 7;
    const unsigned aAddr = sb + (((gq & 2) << 2) + lr) * F1S_KSTRIDE
                         + (yy * 32 + mb + ((gq & 1) << 3)) * 2;
    const unsigned bAddr = sb + F2S_OFF + (((gq & 1) << 3) + lr) * F2S_KSTRIDE
                         + yy * F2S_ROWB + mb * 2;

    // A fragments: loaded once, reused for all 9 di
    unsigned a[4][4];
#pragma unroll
    for (int ks = 0; ks < 4; ks++)
        asm volatile("ldmatrix.sync.aligned.m8n8.x4.trans.shared.b16 {%0,%1,%2,%3}, [%4];"
            : "=r"(a[ks][0]), "=r"(a[ks][1]), "=r"(a[ks][2]), "=r"(a[ks][3])
            : "r"(aAddr + ks * 16 * F1S_KSTRIDE));

    // B fragments: double-buffered across di
    unsigned bf[2][12][2];
#pragma unroll
    for (int q = 0; q < 3; q++)
#pragma unroll
        for (int ks = 0; ks < 4; ks++)
            asm volatile("ldmatrix.sync.aligned.m8n8.x2.trans.shared.b16 {%0,%1}, [%2];"
                : "=r"(bf[0][q*4+ks][0]), "=r"(bf[0][q*4+ks][1])
                : "r"(bAddr + 0 * F2S_ROWB + q * 16 + ks * 16 * F2S_KSTRIDE));

    const int g2 = lane >> 2, tg = lane & 3;
    const float scale = 1.f / 64.f;

#pragma unroll
    for (int di = 0; di < 9; di++) {
        float* epi = (float*)(smem + EPI_OFF + (di & 1) * EPI_SZ);
        const int cur = di & 1, nxt = cur ^ 1;

        // prefetch next di's B fragments (hidden behind MMAs + epilogue)
        if (di < 8) {
#pragma unroll
            for (int q = 0; q < 3; q++)
#pragma unroll
                for (int ks = 0; ks < 4; ks++)
                    asm volatile("ldmatrix.sync.aligned.m8n8.x2.trans.shared.b16 {%0,%1}, [%2];"
                        : "=r"(bf[nxt][q*4+ks][0]), "=r"(bf[nxt][q*4+ks][1])
                        : "r"(bAddr + (di+1) * F2S_ROWB + q * 16 + ks * 16 * F2S_KSTRIDE));
        }

        float acc[3][4];
#pragma unroll
        for (int q = 0; q < 3; q++)
#pragma unroll
            for (int p = 0; p < 4; p++) acc[q][p] = 0.f;

#pragma unroll
        for (int q = 0; q < 3; q++)
#pragma unroll
            for (int ks = 0; ks < 4; ks++)
                asm volatile(
                    "mma.sync.aligned.m16n8k16.row.col.f32.f16.f16.f32 "
                    "{%0,%1,%2,%3}, {%4,%5,%6,%7}, {%8,%9}, {%0,%1,%2,%3};"
                    : "+f"(acc[q][0]), "+f"(acc[q][1]), "+f"(acc[q][2]), "+f"(acc[q][3])
                    : "r"(a[ks][0]), "r"(a[ks][1]), "r"(a[ks][2]), "r"(a[ks][3]),
                      "r"(bf[cur][q*4+ks][0]), "r"(bf[cur][q*4+ks][1]));

        // band extraction: dj = n_local - m_local, keep 0..8
#pragma unroll
        for (int q = 0; q < 3; q++) {
#pragma unroll
            for (int p = 0; p < 4; p++) {
                int m  = g2 + ((p >> 1) << 3);
                int dj = 8 * q + 2 * tg + (p & 1) - m;
                if ((unsigned)dj <= 8u)
                    epi[(dj * YTI + yy) * XTI + mb + m] = acc[q][p];
            }
        }
        __syncthreads();   // epi[di&1] complete; ping-pong protects di+1 writes

        // coalesced store of 9 x 4 x 32 floats
#pragma unroll
        for (int i = 0; i < 5; i++) {
            int idx = tid + i * NTHR;
            if (idx < 9 * YTI * XTI) {
                int dj  = idx / (YTI * XTI);
                int rem = idx - dj * (YTI * XTI);
                int ry = rem >> 5, xx = rem & 31;
                out[((size_t)(b * 81 + di * 9 + dj) * HH + y0 + ry) * WW + x0 + xx]
                    = epi[idx] * scale;
            }
        }
        // no second barrier: next di writes the other epi buffer
    }
}

extern "C" void kernel_launch(void* const* d_in, const int* in_sizes, int n_in,
                              void* d_out, int out_size)
{
    const float* f1 = (const float*)d_in[0];
    const float* f2 = (const float*)d_in[1];
    float* out = (float*)d_out;

    cudaFuncSetAttribute(corr_mma,
                         cudaFuncAttributeMaxDynamicSharedMemorySize, SMEM_TOTAL);
    dim3 grid(WW / XTI, HH / YTI, BB);   // 14 x 48 x 4 = 2688
    corr_mma<<<grid, NTHR, SMEM_TOTAL>>>(f1, f2, out);
}

// round 14
// speedup vs baseline: 1.3075x; 1.0003x over previous
#include <cuda_runtime.h>
#include <cuda_fp16.h>

// Correlation as banded fp16 GEMM (HMMA, fp32 accum), fully fused:
// out[b, di*9+dj, y, x] = (1/64) * sum_c f1[b,c,y,x] * f2pad[b,c,y+di,x+dj]
// Per (b,y,di): C[x,x'] = sum_c f1[c,x]*f2[c,x']; dj = x'-x+4.
// CTA = (b, 4 y-rows, 32 x): m16n8k16 tiles on the 9-wide diagonal band.
// f2 fp32 staged via cp.async ring (no regs), converted fp16 in-CTA.
// Mainloop: single-buffer B fragments (R11 style, regs ~90) — R13's double
// buffering hit the 128-reg cap and lost issue slots.

#define BB 4
#define CC 64
#define HH 192
#define WW 448
#define DD 4

#define YTI 4
#define XTI 32
#define NTHR 256

// smem layout (bytes)
#define F1S_KSTRIDE 272                   // 256 + 16  (16 mod 128 -> LDSM conflict-free)
#define F1S_BYTES   (CC * F1S_KSTRIDE)    // 17408
#define F2S_ROWB    80                    // 40 halves/row, tight
#define F2S_KSTRIDE (12*F2S_ROWB + 16)    // 976 (80 mod 128 = odd*16 -> conflict-free)
#define F2S_OFF     F1S_BYTES
#define F2S_BYTES   (CC * F2S_KSTRIDE)    // 62464
#define STG_OFF     (F2S_OFF + F2S_BYTES) // 79872
#define KG          8                     // channels per staging group
#define NG          (CC / KG)             // 8
#define STG_CH_B    (12 * 160)            // 12 rows x 40 floats
#define STG_BYTES   (KG * STG_CH_B)       // 15360
#define NCHUNK      (KG * 12 * 10)        // 960 16B chunks per group
#define EPI_OFF     STG_OFF               // epi overlays staging after prologue
#define EPI_SZ      (9*YTI*XTI*4)         // 4608
#define SMEM_TOTAL  (STG_OFF + 2*STG_BYTES)  // 110592 -> 2 CTAs/SM

#define GSTRIDE_B   ((size_t)KG * HH * WW * 4)   // gmem bytes per channel-group

__device__ __forceinline__ void cp_async16z(unsigned saddr, const void* gaddr, int sz) {
    asm volatile("cp.async.cg.shared.global [%0], [%1], 16, %2;"
                 :: "r"(saddr), "l"(gaddr), "r"(sz));
}

__global__ __launch_bounds__(NTHR, 2)
void corr_mma(const float* __restrict__ f1,
              const float* __restrict__ f2,
              float* __restrict__ out)
{
    extern __shared__ char smem[];
    const unsigned sb = (unsigned)__cvta_generic_to_shared(smem);
    const int tid  = threadIdx.x;
    const int lane = tid & 31;
    const int w    = tid >> 5;        // 8 warps
    const int yy   = w >> 1;          // warp's y row (0..3)
    const int mb   = (w & 1) * 16;    // warp's m-tile base pixel (0 or 16)
    const int b  = blockIdx.z;
    const int y0 = blockIdx.y * YTI;
    const int x0 = blockIdx.x * XTI;

    const float* f2b = f2 + (size_t)b * CC * HH * WW;

    // ---- per-thread staging chunk descriptors (4 chunks; 4th only for tid<192) ----
    const char* gptr[4];
    int         zsz[4];
    unsigned    stgoff[4];
    unsigned    tileoff[4];
    const int nck = (tid < NCHUNK - 3 * NTHR) ? 4 : 3;
#pragma unroll
    for (int j = 0; j < 4; j++) {
        const int c = (j < nck) ? (tid + j * NTHR) : 0;
        const int ch = c / 120;
        const int rm = c - ch * 120;
        const int r  = rm / 10;
        const int h  = rm - r * 10;
        const int gy = y0 - DD + r;
        const int gx = x0 - DD + 4 * h;    // (x0-4) mult of 4 -> 16B aligned in gmem
        const bool ok = ((unsigned)gy < HH) && (gx >= 0) && (gx + 4 <= WW);
        gptr[j]    = (const char*)(f2b + (size_t)ch * HH * WW
                                   + (ok ? ((size_t)gy * WW + gx) : 0));
        zsz[j]     = ok ? 16 : 0;
        stgoff[j]  = ch * STG_CH_B + r * 160 + h * 16;
        tileoff[j] = ch * F2S_KSTRIDE + r * F2S_ROWB + h * 8;
    }

    auto prefetch = [&](int g, int buf) {
        if (g < NG) {
            const size_t gadd = (size_t)g * GSTRIDE_B;
            const unsigned sbb = sb + STG_OFF + buf * STG_BYTES;
#pragma unroll
            for (int j = 0; j < 4; j++)
                if (j < nck)
                    cp_async16z(sbb + stgoff[j], gptr[j] + gadd, zsz[j]);
        }
        asm volatile("cp.async.commit_group;" ::: "memory");
    };

    prefetch(0, 0);
    prefetch(1, 1);

    // ---- f1 tile: fp32 LDG -> half -> STS (overlaps staging cp.async) ----
    {
        const float* f1b = f1 + (size_t)b * CC * HH * WW;
#pragma unroll
        for (int i = 0; i < 8; i++) {
            const int id = tid + i * NTHR;    // 2048 float4 chunks: 64k x 4y x 8
            const int k  = id >> 5;
            const int rm = id & 31;
            const int ry = rm >> 3;
            const int h  = rm & 7;
            float4 v = *(const float4*)(f1b + ((size_t)k * HH + y0 + ry) * WW + x0 + h * 4);
            __half2 h0 = __floats2half2_rn(v.x, v.y);
            __half2 h1 = __floats2half2_rn(v.z, v.w);
            unsigned s = sb + k * F1S_KSTRIDE + (ry * 32 + h * 4) * 2;
            asm volatile("st.shared.v2.b32 [%0], {%1,%2};"
                         :: "r"(s), "r"(*(unsigned*)&h0), "r"(*(unsigned*)&h1));
        }
    }

    // ---- staged conversion: wait g, convert own chunks, prefetch g+2 ----
#pragma unroll
    for (int g = 0; g < NG; g++) {
        asm volatile("cp.async.wait_group 1;" ::: "memory");
        const int buf = g & 1;
        const char* stg = smem + STG_OFF + buf * STG_BYTES;
        char* tile = smem + F2S_OFF + g * (KG * F2S_KSTRIDE);
#pragma unroll
        for (int j = 0; j < 4; j++) {
            if (j < nck) {
                float4 v = *(const float4*)(stg + stgoff[j]);
                __half2 h0 = __floats2half2_rn(v.x, v.y);
                __half2 h1 = __floats2half2_rn(v.z, v.w);
                uint2 o = make_uint2(*(unsigned*)&h0, *(unsigned*)&h1);
                *(uint2*)(tile + tileoff[j]) = o;
            }
        }
        prefetch(g + 2, buf);
    }

    __syncthreads();   // f1 + f2 fp16 tiles visible to all; staging dead (epi overlay ok)

    // ---- ldmatrix lane addresses (trans: smem is [k][m] / [k][n]) ----
    const int gq = lane >> 3, lr = lane & 7;
    const unsigned aAddr = sb + (((gq & 2) << 2) + lr) * F1S_KSTRIDE
                         + (yy * 32 + mb + ((gq & 1) << 3)) * 2;
    const unsigned bAddr = sb + F2S_OFF + (((gq & 1) << 3) + lr) * F2S_KSTRIDE
                         + yy * F2S_ROWB + mb * 2;

    // A fragments: loaded once, reused for all 9 di
    unsigned a[4][4];
#pragma unroll
    for (int ks = 0; ks < 4; ks++)
        asm volatile("ldmatrix.sync.aligned.m8n8.x4.trans.shared.b16 {%0,%1,%2,%3}, [%4];"
            : "=r"(a[ks][0]), "=r"(a[ks][1]), "=r"(a[ks][2]), "=r"(a[ks][3])
            : "r"(aAddr + ks * 16 * F1S_KSTRIDE));

    const int g2 = lane >> 2, tg = lane & 3;
    const float scale = 1.f / 64.f;

    for (int di = 0; di < 9; di++) {
        float* epi = (float*)(smem + EPI_OFF + (di & 1) * EPI_SZ);

        float acc[3][4];
#pragma unroll
        for (int q = 0; q < 3; q++)
#pragma unroll
            for (int p = 0; p < 4; p++) acc[q][p] = 0.f;

#pragma unroll
        for (int q = 0; q < 3; q++) {
#pragma unroll
            for (int ks = 0; ks < 4; ks++) {
                unsigned b0, b1;
                asm volatile("ldmatrix.sync.aligned.m8n8.x2.trans.shared.b16 {%0,%1}, [%2];"
                    : "=r"(b0), "=r"(b1)
                    : "r"(bAddr + di * F2S_ROWB + q * 16 + ks * 16 * F2S_KSTRIDE));
                asm volatile(
                    "mma.sync.aligned.m16n8k16.row.col.f32.f16.f16.f32 "
                    "{%0,%1,%2,%3}, {%4,%5,%6,%7}, {%8,%9}, {%0,%1,%2,%3};"
                    : "+f"(acc[q][0]), "+f"(acc[q][1]), "+f"(acc[q][2]), "+f"(acc[q][3])
                    : "r"(a[ks][0]), "r"(a[ks][1]), "r"(a[ks][2]), "r"(a[ks][3]),
                      "r"(b0), "r"(b1));
            }
        }

        // band extraction: dj = n_local - m_local, keep 0..8
#pragma unroll
        for (int q = 0; q < 3; q++) {
#pragma unroll
            for (int p = 0; p < 4; p++) {
                int m  = g2 + ((p >> 1) << 3);
                int dj = 8 * q + 2 * tg + (p & 1) - m;
                if ((unsigned)dj <= 8u)
                    epi[(dj * YTI + yy) * XTI + mb + m] = acc[q][p];
            }
        }
        __syncthreads();   // epi[di&1] complete; ping-pong protects di+1 writes

        // coalesced store of 9 x 4 x 32 floats
#pragma unroll
        for (int i = 0; i < 5; i++) {
            int idx = tid + i * NTHR;
            if (idx < 9 * YTI * XTI) {
                int dj  = idx / (YTI * XTI);
                int rem = idx - dj * (YTI * XTI);
                int ry = rem >> 5, xx = rem & 31;
                out[((size_t)(b * 81 + di * 9 + dj) * HH + y0 + ry) * WW + x0 + xx]
                    = epi[idx] * scale;
            }
        }
        // no second barrier: next di writes the other epi buffer
    }
}

extern "C" void kernel_launch(void* const* d_in, const int* in_sizes, int n_in,
                              void* d_out, int out_size)
{
    const float* f1 = (const float*)d_in[0];
    const float* f2 = (const float*)d_in[1];
    float* out = (float*)d_out;

    cudaFuncSetAttribute(corr_mma,
                         cudaFuncAttributeMaxDynamicSharedMemorySize, SMEM_TOTAL);
    dim3 grid(WW / XTI, HH / YTI, BB);   // 14 x 48 x 4 = 2688
    corr_mma<<<grid, NTHR, SMEM_TOTAL>>>(f1, f2, out);
}

// round 15
// speedup vs baseline: 1.4729x; 1.1265x over previous
#include <cuda_runtime.h>
#include <cuda_fp16.h>

// Correlation as banded fp16 GEMM (HMMA, fp32 accum), fully fused:
// out[b, di*9+dj, y, x] = (1/64) * sum_c f1[b,c,y,x] * f2pad[b,c,y+di,x+dj]
// Per (b,y,di): C[x,x'] = sum_c f1[c,x]*f2[c,x']; dj = x'-x+4.
// CTA = (b, 4 y-rows, 32 x). 512 threads / 16 warps: warp = (yy, mb, di-parity),
// warp-private epilogue (no CTA barriers in mainloop) -> 32 warps/SM resident.

#define BB 4
#define CC 64
#define HH 192
#define WW 448
#define DD 4

#define YTI 4
#define XTI 32
#define NTHR 512

// smem layout (bytes)
#define F1S_KSTRIDE 272                   // 256 + 16  (16 mod 128 -> LDSM conflict-free)
#define F1S_BYTES   (CC * F1S_KSTRIDE)    // 17408
#define F2S_ROWB    80                    // 40 halves/row
#define F2S_KSTRIDE (12*F2S_ROWB + 16)    // 976 (odd*16 -> LDSM conflict-free)
#define F2S_OFF     F1S_BYTES
#define F2S_BYTES   (CC * F2S_KSTRIDE)    // 62464
#define STG_OFF     (F2S_OFF + F2S_BYTES) // 79872
#define KG          8                     // channels per staging group
#define NG          (CC / KG)             // 8
#define STG_CH_B    (12 * 160)            // 12 rows x 40 floats
#define STG_BYTES   (KG * STG_CH_B)       // 15360
#define NCHUNK      (KG * 12 * 10)        // 960 16B chunks per group
#define SLAB_OFF    STG_OFF               // warp-private epi slabs overlay staging
#define SLAB_B      672                   // 9 rows x 18 floats (pad), 16B-aligned
#define SMEM_TOTAL  (STG_OFF + 2*STG_BYTES)  // 110592 -> 2 CTAs/SM (221KB)

#define GSTRIDE_B   ((size_t)KG * HH * WW * 4)

__device__ __forceinline__ void cp_async16z(unsigned saddr, const void* gaddr, int sz) {
    asm volatile("cp.async.cg.shared.global [%0], [%1], 16, %2;"
                 :: "r"(saddr), "l"(gaddr), "r"(sz));
}

__global__ __launch_bounds__(NTHR, 2)
void corr_mma(const float* __restrict__ f1,
              const float* __restrict__ f2,
              float* __restrict__ out)
{
    extern __shared__ char smem[];
    const unsigned sb = (unsigned)__cvta_generic_to_shared(smem);
    const int tid  = threadIdx.x;
    const int lane = tid & 31;
    const int w    = tid >> 5;          // 16 warps
    const int yy   = w >> 2;            // 0..3
    const int mb   = ((w >> 1) & 1) * 16;
    const int dih  = w & 1;             // di parity
    const int b  = blockIdx.z;
    const int y0 = blockIdx.y * YTI;
    const int x0 = blockIdx.x * XTI;

    const float* f2b = f2 + (size_t)b * CC * HH * WW;

    // ---- per-thread staging chunk descriptors (2 chunks; 2nd for tid<448) ----
    const char* gptr[2];
    int         zsz[2];
    unsigned    stgoff[2];
    unsigned    tileoff[2];
    const int nck = (tid < NCHUNK - NTHR) ? 2 : 1;
#pragma unroll
    for (int j = 0; j < 2; j++) {
        const int c = (j < nck) ? (tid + j * NTHR) : 0;
        const int ch = c / 120;
        const int rm = c - ch * 120;
        const int r  = rm / 10;
        const int h  = rm - r * 10;
        const int gy = y0 - DD + r;
        const int gx = x0 - DD + 4 * h;   // 16B aligned in gmem
        const bool ok = ((unsigned)gy < HH) && (gx >= 0) && (gx + 4 <= WW);
        gptr[j]    = (const char*)(f2b + (size_t)ch * HH * WW
                                   + (ok ? ((size_t)gy * WW + gx) : 0));
        zsz[j]     = ok ? 16 : 0;
        stgoff[j]  = ch * STG_CH_B + r * 160 + h * 16;
        tileoff[j] = ch * F2S_KSTRIDE + r * F2S_ROWB + h * 8;
    }

    auto prefetch = [&](int g, int buf) {
        if (g < NG) {
            const size_t gadd = (size_t)g * GSTRIDE_B;
            const unsigned sbb = sb + STG_OFF + buf * STG_BYTES;
#pragma unroll
            for (int j = 0; j < 2; j++)
                if (j < nck)
                    cp_async16z(sbb + stgoff[j], gptr[j] + gadd, zsz[j]);
        }
        asm volatile("cp.async.commit_group;" ::: "memory");
    };

    prefetch(0, 0);
    prefetch(1, 1);

    // ---- f1 tile: fp32 LDG -> half -> STS (overlaps staging cp.async) ----
    {
        const float* f1b = f1 + (size_t)b * CC * HH * WW;
#pragma unroll
        for (int i = 0; i < 4; i++) {
            const int id = tid + i * NTHR;    // 2048 float4 chunks: 64k x 4y x 8
            const int k  = id >> 5;
            const int rm = id & 31;
            const int ry = rm >> 3;
            const int h  = rm & 7;
            float4 v = *(const float4*)(f1b + ((size_t)k * HH + y0 + ry) * WW + x0 + h * 4);
            __half2 h0 = __floats2half2_rn(v.x, v.y);
            __half2 h1 = __floats2half2_rn(v.z, v.w);
            unsigned s = sb + k * F1S_KSTRIDE + (ry * 32 + h * 4) * 2;
            asm volatile("st.shared.v2.b32 [%0], {%1,%2};"
                         :: "r"(s), "r"(*(unsigned*)&h0), "r"(*(unsigned*)&h1));
        }
    }

    // ---- staged conversion: wait g, convert own chunks, prefetch g+2 ----
#pragma unroll
    for (int g = 0; g < NG; g++) {
        asm volatile("cp.async.wait_group 1;" ::: "memory");
        const int buf = g & 1;
        const char* stg = smem + STG_OFF + buf * STG_BYTES;
        char* tile = smem + F2S_OFF + g * (KG * F2S_KSTRIDE);
#pragma unroll
        for (int j = 0; j < 2; j++) {
            if (j < nck) {
                float4 v = *(const float4*)(stg + stgoff[j]);
                __half2 h0 = __floats2half2_rn(v.x, v.y);
                __half2 h1 = __floats2half2_rn(v.z, v.w);
                uint2 o = make_uint2(*(unsigned*)&h0, *(unsigned*)&h1);
                *(uint2*)(tile + tileoff[j]) = o;
            }
        }
        prefetch(g + 2, buf);
    }

    __syncthreads();   // tiles visible; staging dead (slab overlay safe)

    // ---- ldmatrix lane addresses (trans: smem is [k][m] / [k][n]) ----
    const int gq = lane >> 3, lr = lane & 7;
    const unsigned aAddr = sb + (((gq & 2) << 2) + lr) * F1S_KSTRIDE
                         + (yy * 32 + mb + ((gq & 1) << 3)) * 2;
    const unsigned bAddr = sb + F2S_OFF + (((gq & 1) << 3) + lr) * F2S_KSTRIDE
                         + yy * F2S_ROWB + mb * 2;

    // A fragments: loaded once per warp, reused for its di subset
    unsigned a[4][4];
#pragma unroll
    for (int ks = 0; ks < 4; ks++)
        asm volatile("ldmatrix.sync.aligned.m8n8.x4.trans.shared.b16 {%0,%1,%2,%3}, [%4];"
            : "=r"(a[ks][0]), "=r"(a[ks][1]), "=r"(a[ks][2]), "=r"(a[ks][3])
            : "r"(aAddr + ks * 16 * F1S_KSTRIDE));

    float* slab = (float*)(smem + SLAB_OFF + w * SLAB_B);
    const int g2 = lane >> 2, tg = lane & 3;
    const float scale = 1.f / 64.f;

    // warp-private mainloop: di = dih, dih+2, ... (no CTA barriers)
    for (int di = dih; di < 9; di += 2) {
        float acc[3][4];
#pragma unroll
        for (int q = 0; q < 3; q++)
#pragma unroll
            for (int p = 0; p < 4; p++) acc[q][p] = 0.f;

#pragma unroll
        for (int q = 0; q < 3; q++) {
#pragma unroll
            for (int ks = 0; ks < 4; ks++) {
                unsigned b0, b1;
                asm volatile("ldmatrix.sync.aligned.m8n8.x2.trans.shared.b16 {%0,%1}, [%2];"
                    : "=r"(b0), "=r"(b1)
                    : "r"(bAddr + di * F2S_ROWB + q * 16 + ks * 16 * F2S_KSTRIDE));
                asm volatile(
                    "mma.sync.aligned.m16n8k16.row.col.f32.f16.f16.f32 "
                    "{%0,%1,%2,%3}, {%4,%5,%6,%7}, {%8,%9}, {%0,%1,%2,%3};"
                    : "+f"(acc[q][0]), "+f"(acc[q][1]), "+f"(acc[q][2]), "+f"(acc[q][3])
                    : "r"(a[ks][0]), "r"(a[ks][1]), "r"(a[ks][2]), "r"(a[ks][3]),
                      "r"(b0), "r"(b1));
            }
        }

        // band extraction into warp-private slab: dj = n_local - m_local in 0..8
#pragma unroll
        for (int q = 0; q < 3; q++) {
#pragma unroll
            for (int p = 0; p < 4; p++) {
                int m  = g2 + ((p >> 1) << 3);
                int dj = 8 * q + 2 * tg + (p & 1) - m;
                if ((unsigned)dj <= 8u)
                    slab[dj * 18 + m] = acc[q][p];
            }
        }
        __syncwarp();

        // store: two dj rows per iter, 16-float contiguous segments
#pragma unroll
        for (int r = 0; r < 5; r++) {
            int dj = 2 * r + (lane >> 4);
            int xx = lane & 15;
            if (dj < 9)
                out[((size_t)(b * 81 + di * 9 + dj) * HH + y0 + yy) * WW + x0 + mb + xx]
                    = slab[dj * 18 + xx] * scale;
        }
        __syncwarp();   // slab reuse next di
    }
}

extern "C" void kernel_launch(void* const* d_in, const int* in_sizes, int n_in,
                              void* d_out, int out_size)
{
    const float* f1 = (const float*)d_in[0];
    const float* f2 = (const float*)d_in[1];
    float* out = (float*)d_out;

    cudaFuncSetAttribute(corr_mma,
                         cudaFuncAttributeMaxDynamicSharedMemorySize, SMEM_TOTAL);
    dim3 grid(WW / XTI, HH / YTI, BB);   // 14 x 48 x 4 = 2688
    corr_mma<<<grid, NTHR, SMEM_TOTAL>>>(f1, f2, out);
}